// round 11
// baseline (speedup 1.0000x reference)
#include <cuda_runtime.h>
#include <cstdint>

#define SEQ     512
#define BATCH   64
#define HID     1024
#define TWOH    2048
#define NLAYER  2
#define NDEPTH  4

#define GRID    128      // CTAs; each owns 8 hidden columns (+ paired gate cols)
#define NTH     256
#define KC      32       // K-chunk
#define CPC     8        // h-columns per CTA  (HID / GRID)

// ---------------- device scratch (no cudaMalloc allowed) ----------------
__device__ float    g_S[NLAYER][2][BATCH * HID];   // double-buffered state
__device__ unsigned g_bar_count;
__device__ unsigned g_bar_gen;

// ---------------- software grid barrier (128 co-resident CTAs) ----------
__device__ __forceinline__ void grid_barrier() {
    __syncthreads();
    if (threadIdx.x == 0) {
        __threadfence();                         // publish this CTA's stores
        volatile unsigned* genp = &g_bar_gen;
        unsigned gen = *genp;
        if (atomicAdd(&g_bar_count, 1u) == GRID - 1u) {
            atomicExch(&g_bar_count, 0u);
            __threadfence();
            atomicExch(&g_bar_gen, gen + 1u);    // release
        } else {
            while (*genp == gen) { __nanosleep(40); }
            __threadfence();                     // acquire
        }
    }
    __syncthreads();
}

// ---------------- one GEMM accumulation pass: acc += A[64,1024] @ W cols --
// CTA c owns 16 weight columns: h-cols [c*8, c*8+8) and g-cols [1024+c*8, ...).
// Thread (r = tid&63, g4 = tid>>6) accumulates row r, 4 columns (g4*4..+3).
__device__ __forceinline__ void gemm_acc(
    const float* __restrict__ A,       // [64, 1024]  (state / input; read via .cg)
    const float* __restrict__ W,       // [1024, 2048] row-major
    float* s_sm, float* w_sm,
    int c, int tid, float4& acc)
{
    const int lrow = tid >> 2;          // 0..63 : row this thread loads for s-tile
    const int lq8  = (tid & 3) * 8;     // 8-float segment within 32-float k-chunk
    const int r    = tid & 63;
    const int g4   = tid >> 6;

    // W tile load mapping: 32 k × 16 n, 2 consecutive n per thread
    const int wk = tid >> 3;            // (tid*2)/16 = k row 0..31
    const int wn = (tid * 2) & 15;      // 0,2,..,14
    const int wcol = (wn < 8) ? (c * CPC + wn) : (HID + c * CPC + (wn - 8));

    const float* arow = s_sm + r * 33;
    const float* wqp  = w_sm + g4 * 4;

#pragma unroll 1
    for (int k0 = 0; k0 < HID; k0 += KC) {
        // stage next tiles (A must bypass L1: written by other SMs last step)
        float4 a0 = __ldcg((const float4*)(A + lrow * HID + k0 + lq8));
        float4 a1 = __ldcg((const float4*)(A + lrow * HID + k0 + lq8 + 4));
        float2 wv = *(const float2*)(W + (size_t)(k0 + wk) * TWOH + wcol);
        __syncthreads();                // previous chunk's reads done
        float* sd = s_sm + lrow * 33 + lq8;
        sd[0] = a0.x; sd[1] = a0.y; sd[2] = a0.z; sd[3] = a0.w;
        sd[4] = a1.x; sd[5] = a1.y; sd[6] = a1.z; sd[7] = a1.w;
        w_sm[wk * 16 + wn]     = wv.x;
        w_sm[wk * 16 + wn + 1] = wv.y;
        __syncthreads();
#pragma unroll
        for (int kk = 0; kk < KC; kk++) {
            float a = arow[kk];                              // conflict-free (pad 33)
            const float4 wq = *(const float4*)(wqp + kk * 16); // broadcast LDS.128
            acc.x = fmaf(a, wq.x, acc.x);
            acc.y = fmaf(a, wq.y, acc.y);
            acc.z = fmaf(a, wq.z, acc.z);
            acc.w = fmaf(a, wq.w, acc.w);
        }
    }
}

// ---------------- persistent RHN kernel ---------------------------------
__global__ void __launch_bounds__(NTH) rhn_kernel(
    const float* __restrict__ x,     // [512, 64, 1024]
    const float* __restrict__ st0,   // [2, 64, 1024]
    const float* __restrict__ w_in,  // [2, 1024, 2048]
    const float* __restrict__ w_h,   // [2, 4, 1024, 2048]
    const float* __restrict__ b_h,   // [2, 4, 2048]
    float* __restrict__ out)         // [512,64,1024] ++ [2,64,1024]
{
    __shared__ float s_sm[64 * 33];
    __shared__ float w_sm[KC * 16];
    __shared__ float hg_sm[64 * 17];

    const int c   = blockIdx.x;
    const int tid = threadIdx.x;
    const int r   = tid & 63;
    const int g4  = tid >> 6;

    // init state (each CTA its own 8 columns, both layers) into parity 0
    for (int i = tid; i < NLAYER * BATCH * CPC; i += NTH) {
        int l = i >> 9;
        int b = (i >> 3) & 63;
        int j = i & 7;
        int col = c * CPC + j;
        g_S[l][0][b * HID + col] = st0[(size_t)l * BATCH * HID + b * HID + col];
    }
    grid_barrier();

    const int nloc  = g4 * 4;                                   // local col 0..15
    const int nglob = (nloc < 8) ? (c * CPC + nloc)             // global weight col
                                 : (HID + c * CPC + (nloc - 8));

#pragma unroll 1
    for (int t = 0; t < SEQ; t++) {
        const float* xt = x + (size_t)t * BATCH * HID;
#pragma unroll 1
        for (int l = 0; l < NLAYER; l++) {
            // layer input: x_t for layer 0, layer 0's finished state (parity 0) above
            const float* inp = (l == 0) ? xt : g_S[0][0];
#pragma unroll 1
            for (int d = 0; d < NDEPTH; d++) {
                const float* scur = g_S[l][d & 1];
                float*       snxt = g_S[l][(d + 1) & 1];
                const float* W = w_h + (size_t)(l * NDEPTH + d) * HID * TWOH;

                float4 acc = make_float4(0.f, 0.f, 0.f, 0.f);
                gemm_acc(scur, W, s_sm, w_sm, c, tid, acc);
                if (d == 0) {
                    const float* Wi = w_in + (size_t)l * HID * TWOH;
                    gemm_acc(inp, Wi, s_sm, w_sm, c, tid, acc);   // hg0 enters depth 0
                }
                // bias
                const float4 bv = *(const float4*)(
                    b_h + (size_t)(l * NDEPTH + d) * TWOH + nglob);
                acc.x += bv.x; acc.y += bv.y; acc.z += bv.z; acc.w += bv.w;

                // exchange h/g halves through smem, then gated update
                float* hd = hg_sm + r * 17 + nloc;
                hd[0] = acc.x; hd[1] = acc.y; hd[2] = acc.z; hd[3] = acc.w;
                __syncthreads();
                for (int i = tid; i < BATCH * CPC; i += NTH) {
                    int b = i >> 3, j = i & 7;
                    float hh = hg_sm[b * 17 + j];
                    float hg = hg_sm[b * 17 + 8 + j];
                    float hv = tanhf(hh);
                    float gv = 1.0f / (1.0f + expf(-hg));
                    int col = c * CPC + j;
                    float sold = __ldcg(scur + b * HID + col);
                    float sn = fmaf(gv, hv - sold, sold);   // h*g + s*(1-g)
                    snxt[b * HID + col] = sn;
                    if (l == NLAYER - 1 && d == NDEPTH - 1)
                        out[(size_t)t * BATCH * HID + b * HID + col] = sn;
                }
                grid_barrier();
            }
        }
    }

    // final_s (both layers end each timestep at parity 0)
    const size_t fin = (size_t)SEQ * BATCH * HID;
    for (int i = tid; i < NLAYER * BATCH * CPC; i += NTH) {
        int l = i >> 9;
        int b = (i >> 3) & 63;
        int j = i & 7;
        int col = c * CPC + j;
        out[fin + (size_t)l * BATCH * HID + b * HID + col] = g_S[l][0][b * HID + col];
    }
}

// ---------------- launch -------------------------------------------------
extern "C" void kernel_launch(void* const* d_in, const int* in_sizes, int n_in,
                              void* d_out, int out_size) {
    const float* x   = (const float*)d_in[0];   // x      [512,64,1024]
    const float* st  = (const float*)d_in[1];   // state  [2,64,1024]
    const float* wi  = (const float*)d_in[2];   // w_in   [2,1024,2048]
    const float* wh  = (const float*)d_in[3];   // w_h    [2,4,1024,2048]
    const float* bh  = (const float*)d_in[4];   // b_h    [2,4,2048]
    (void)in_sizes; (void)n_in; (void)out_size;
    rhn_kernel<<<GRID, NTH>>>(x, st, wi, wh, bh, (float*)d_out);
}

// round 12
// speedup vs baseline: 1.6347x; 1.6347x over previous
#include <cuda_runtime.h>
#include <cstdint>

#define SEQ     512
#define BATCH   64
#define HID     1024
#define TWOH    2048
#define NLAYER  2
#define NDEPTH  4

#define GRID    128      // CTAs; each owns 8 h-columns + paired 8 g-columns
#define NTH     512
#define KC      64       // K-chunk
#define NCH     (HID / KC)   // 16
#define SPAD    65       // s-tile row stride (odd -> conflict-free)
#define CPC     8        // h-columns per CTA

// ---------------- device scratch (no cudaMalloc allowed) ----------------
__device__ float    g_S[NLAYER][2][BATCH * HID];   // double-buffered state
__device__ unsigned g_bar_count;
__device__ unsigned g_bar_gen;

// ---------------- software grid barrier (128 co-resident CTAs) ----------
__device__ __forceinline__ void grid_barrier() {
    __syncthreads();
    if (threadIdx.x == 0) {
        __threadfence();                         // publish this CTA's stores
        volatile unsigned* genp = &g_bar_gen;
        unsigned gen = *genp;
        if (atomicAdd(&g_bar_count, 1u) == GRID - 1u) {
            atomicExch(&g_bar_count, 0u);        // reset BEFORE release
            __threadfence();
            atomicExch(&g_bar_gen, gen + 1u);    // release
        } else {
            while (*genp == gen) {}
            __threadfence();                     // acquire
        }
    }
    __syncthreads();
}

// ---------------- one GEMM pass: acc += A[64,1024] @ W[:, 16 CTA cols] ---
// Double-buffered smem, 1 sync per K-chunk. Thread (r = tid&63, cl = (tid>>6)*2)
// accumulates row r, local cols cl, cl+1.
__device__ __forceinline__ void gemm_acc(
    const float* __restrict__ A,       // [64,1024]; MUST bypass L1 (ldcg)
    const float* __restrict__ W,       // [1024,2048]; immutable -> L1 ok
    float* __restrict__ s_sm,          // [2][64*SPAD]
    float* __restrict__ w_sm,          // [2][KC*16]
    int wcol, int tid, int r, int cl,
    float& a0, float& a1)
{
    const int lrow = tid >> 3;          // 0..63 : A row this thread stages
    const int lq   = (tid & 7) * 8;     // 8-float segment of 64-float k-chunk
    const int wk   = tid >> 3;          // 0..63 : W k-row this thread stages
    const int wn   = (tid & 7) * 2;     // 0,2,..,14 local col pair (never crosses h|g)

    // prologue: stage chunk 0
    float4 ra0 = __ldcg((const float4*)(A + lrow * HID + lq));
    float4 ra1 = __ldcg((const float4*)(A + lrow * HID + lq + 4));
    float2 rw  = *(const float2*)(W + (size_t)wk * TWOH + wcol);
    {
        float* sd = s_sm + lrow * SPAD + lq;
        sd[0]=ra0.x; sd[1]=ra0.y; sd[2]=ra0.z; sd[3]=ra0.w;
        sd[4]=ra1.x; sd[5]=ra1.y; sd[6]=ra1.z; sd[7]=ra1.w;
        float* wd = w_sm + wk * 16 + wn;
        wd[0]=rw.x; wd[1]=rw.y;
    }
    __syncthreads();

#pragma unroll 1
    for (int ch = 0; ch < NCH; ch++) {
        // prefetch next chunk into registers (overlaps compute below)
        if (ch + 1 < NCH) {
            const int k0 = (ch + 1) * KC;
            ra0 = __ldcg((const float4*)(A + lrow * HID + k0 + lq));
            ra1 = __ldcg((const float4*)(A + lrow * HID + k0 + lq + 4));
            rw  = *(const float2*)(W + (size_t)(k0 + wk) * TWOH + wcol);
        }
        // compute current chunk
        const float* arow = s_sm + (ch & 1) * (64 * SPAD) + r * SPAD;
        const float* wp   = w_sm + (ch & 1) * (KC * 16) + cl;
#pragma unroll
        for (int kk = 0; kk < KC; kk++) {
            float a = arow[kk];                               // conflict-free LDS
            float2 w = *(const float2*)(wp + kk * 16);        // warp-uniform LDS.64
            a0 = fmaf(a, w.x, a0);
            a1 = fmaf(a, w.y, a1);
        }
        // stage next chunk into the other buffer
        if (ch + 1 < NCH) {
            const int nb = (ch + 1) & 1;
            float* sd = s_sm + nb * (64 * SPAD) + lrow * SPAD + lq;
            sd[0]=ra0.x; sd[1]=ra0.y; sd[2]=ra0.z; sd[3]=ra0.w;
            sd[4]=ra1.x; sd[5]=ra1.y; sd[6]=ra1.z; sd[7]=ra1.w;
            float* wd = w_sm + nb * (KC * 16) + wk * 16 + wn;
            wd[0]=rw.x; wd[1]=rw.y;
        }
        __syncthreads();
    }
}

// ---------------- persistent RHN kernel ---------------------------------
__global__ void __launch_bounds__(NTH, 1) rhn_kernel(
    const float* __restrict__ x,     // [512, 64, 1024]
    const float* __restrict__ st0,   // [2, 64, 1024]
    const float* __restrict__ w_in,  // [2, 1024, 2048]
    const float* __restrict__ w_h,   // [2, 4, 1024, 2048]
    const float* __restrict__ b_h,   // [2, 4, 2048]
    float* __restrict__ out)         // [512,64,1024] ++ [2,64,1024]
{
    __shared__ float s_sm[2 * 64 * SPAD];
    __shared__ float w_sm[2 * KC * 16];
    __shared__ float hg_sm[64 * 17];

    const int c   = blockIdx.x;
    const int tid = threadIdx.x;
    const int r   = tid & 63;
    const int cl  = (tid >> 6) * 2;     // local cols cl, cl+1 (0..15)

    // global weight columns
    const int wn   = (tid & 7) * 2;     // staging col pair
    const int wcol = (wn < 8) ? (c * CPC + wn) : (HID + c * CPC + (wn - 8));
    const int nglob = (cl < 8) ? (c * CPC + cl) : (HID + c * CPC + (cl - 8));

    // init state into parity 0 (each CTA its own 8 columns, both layers)
    for (int i = tid; i < NLAYER * BATCH * CPC; i += NTH) {
        int l = i >> 9;
        int b = (i >> 3) & 63;
        int j = i & 7;
        int col = c * CPC + j;
        g_S[l][0][b * HID + col] = st0[(size_t)l * BATCH * HID + b * HID + col];
    }
    grid_barrier();

#pragma unroll 1
    for (int t = 0; t < SEQ; t++) {
        const float* xt = x + (size_t)t * BATCH * HID;
#pragma unroll 1
        for (int l = 0; l < NLAYER; l++) {
            const float* inp = (l == 0) ? xt : g_S[0][0];   // layer 0 out at parity 0
#pragma unroll 1
            for (int d = 0; d < NDEPTH; d++) {
                const float* scur = g_S[l][d & 1];
                float*       snxt = g_S[l][(d + 1) & 1];
                const float* W = w_h + (size_t)(l * NDEPTH + d) * HID * TWOH;

                float a0 = 0.f, a1 = 0.f;
                gemm_acc(scur, W, s_sm, w_sm, wcol, tid, r, cl, a0, a1);
                if (d == 0) {
                    const float* Wi = w_in + (size_t)l * HID * TWOH;
                    gemm_acc(inp, Wi, s_sm, w_sm, wcol, tid, r, cl, a0, a1);
                }
                // bias
                const float2 bv = *(const float2*)(
                    b_h + (size_t)(l * NDEPTH + d) * TWOH + nglob);
                a0 += bv.x; a1 += bv.y;

                // exchange h/g halves through smem, then gated update
                hg_sm[r * 17 + cl]     = a0;
                hg_sm[r * 17 + cl + 1] = a1;
                __syncthreads();
                {
                    int b = tid >> 3, j = tid & 7;           // 512 = 64*8 elements
                    float hh = hg_sm[b * 17 + j];
                    float hg = hg_sm[b * 17 + 8 + j];
                    float hv = tanhf(hh);
                    float gv = 1.0f / (1.0f + expf(-hg));
                    int col = c * CPC + j;
                    float sold = __ldcg(scur + b * HID + col);
                    float sn = fmaf(gv, hv - sold, sold);    // h*g + s*(1-g)
                    snxt[b * HID + col] = sn;
                    if (l == NLAYER - 1 && d == NDEPTH - 1)
                        out[(size_t)t * BATCH * HID + b * HID + col] = sn;
                }
                grid_barrier();
            }
        }
    }

    // final_s (both layers end each timestep at parity 0)
    const size_t fin = (size_t)SEQ * BATCH * HID;
    for (int i = tid; i < NLAYER * BATCH * CPC; i += NTH) {
        int l = i >> 9;
        int b = (i >> 3) & 63;
        int j = i & 7;
        int col = c * CPC + j;
        out[fin + (size_t)l * BATCH * HID + b * HID + col] = g_S[l][0][b * HID + col];
    }
}

// ---------------- launch -------------------------------------------------
extern "C" void kernel_launch(void* const* d_in, const int* in_sizes, int n_in,
                              void* d_out, int out_size) {
    const float* x   = (const float*)d_in[0];   // x      [512,64,1024]
    const float* st  = (const float*)d_in[1];   // state  [2,64,1024]
    const float* wi  = (const float*)d_in[2];   // w_in   [2,1024,2048]
    const float* wh  = (const float*)d_in[3];   // w_h    [2,4,1024,2048]
    const float* bh  = (const float*)d_in[4];   // b_h    [2,4,2048]
    (void)in_sizes; (void)n_in; (void)out_size;
    rhn_kernel<<<GRID, NTH>>>(x, st, wi, wh, bh, (float*)d_out);
}

// round 15
// speedup vs baseline: 2.2261x; 1.3618x over previous
#include <cuda_runtime.h>
#include <cstdint>

#define SEQ     512
#define BATCH   64
#define HID     1024
#define TWOH    2048
#define NLAYER  2
#define NDEPTH  4

#define GRID    128      // CTAs; each owns 8 h-cols + paired 8 g-cols
#define NTH     512
#define KC      64       // K-chunk
#define NCH     (HID / KC)   // 16
#define SPAD    65       // s-tile row stride (odd -> conflict-free)
#define CPC     8        // h-columns per CTA

// shared pool layout (floats)
#define S_OFF   0                 // s-tiles: 2 * 64 * SPAD = 8320
#define W_OFF   (2 * 64 * SPAD)   // w-tiles: 2 * KC * 16  = 2048
#define POOLSZ  (W_OFF + 2 * KC * 16)   // 10368 floats = 41472 B
#define RED_OFF 0                 // reduction buf aliases s-tiles (after GEMM done)

// ---------------- device scratch (no cudaMalloc allowed) ----------------
__device__ float    g_S[NLAYER][2][BATCH * HID];   // double-buffered state
__device__ unsigned g_bar_count;
__device__ unsigned g_bar_gen;

// ---------------- software grid barrier (128 co-resident CTAs) ----------
__device__ __forceinline__ void grid_barrier() {
    __syncthreads();
    if (threadIdx.x == 0) {
        __threadfence();                         // publish this CTA's stores
        volatile unsigned* genp = &g_bar_gen;
        unsigned gen = *genp;
        if (atomicAdd(&g_bar_count, 1u) == GRID - 1u) {
            atomicExch(&g_bar_count, 0u);        // reset BEFORE release
            __threadfence();
            atomicExch(&g_bar_gen, gen + 1u);    // release
        } else {
            while (*genp == gen) {}
            __threadfence();                     // acquire
        }
    }
    __syncthreads();
}

// ---------------- one GEMM pass: acc += A[64,1024] @ W[:, 16 CTA cols] ---
// Thread (rg = tid&31, cg = (tid>>5)&3, ks = tid>>7) accumulates rows
// {rg, rg+32} x cols [cg*4, cg*4+4) over k = 4*kk + ks (interleaved split-K).
__device__ __forceinline__ void gemm_acc(
    const float* __restrict__ A,       // [64,1024]; bypass L1 (state is remote-written)
    const float* __restrict__ W,       // [1024,2048]; immutable -> L1 ok
    float* __restrict__ pool,
    int wcol, int tid, float* acc)
{
    const int rg  = tid & 31;
    const int cg4 = ((tid >> 5) & 3) * 4;
    const int ks  = tid >> 7;

    const int lrow = tid >> 3;          // 0..63 : A row this thread stages
    const int lq   = (tid & 7) * 8;     // 8-float segment of 64-float chunk
    const int wk   = tid >> 3;          // 0..63 : W k-row this thread stages
    const int wn   = (tid & 7) * 2;     // staging col pair

    float* s_sm = pool + S_OFF;
    float* w_sm = pool + W_OFF;

    // prologue: stage chunk 0
    float4 ra0 = __ldcg((const float4*)(A + lrow * HID + lq));
    float4 ra1 = __ldcg((const float4*)(A + lrow * HID + lq + 4));
    float2 rw  = *(const float2*)(W + (size_t)wk * TWOH + wcol);
    {
        float* sd = s_sm + lrow * SPAD + lq;
        sd[0]=ra0.x; sd[1]=ra0.y; sd[2]=ra0.z; sd[3]=ra0.w;
        sd[4]=ra1.x; sd[5]=ra1.y; sd[6]=ra1.z; sd[7]=ra1.w;
        float* wd = w_sm + wk * 16 + wn;
        wd[0]=rw.x; wd[1]=rw.y;
    }
    __syncthreads();

#pragma unroll 1
    for (int ch = 0; ch < NCH; ch++) {
        // prefetch next chunk into registers (overlaps compute)
        if (ch + 1 < NCH) {
            const int k0 = (ch + 1) * KC;
            ra0 = __ldcg((const float4*)(A + lrow * HID + k0 + lq));
            ra1 = __ldcg((const float4*)(A + lrow * HID + k0 + lq + 4));
            rw  = *(const float2*)(W + (size_t)(k0 + wk) * TWOH + wcol);
        }
        // compute current chunk: 16 interleaved k's for this k-slice
        const float* sb = s_sm + (ch & 1) * (64 * SPAD);
        const float* wb = w_sm + (ch & 1) * (KC * 16);
        const float* arow0 = sb + rg * SPAD + ks;
        const float* arow1 = sb + (rg + 32) * SPAD + ks;
        const float* wp    = wb + ks * 16 + cg4;
#pragma unroll
        for (int kk = 0; kk < KC / 4; kk++) {
            float a0 = arow0[kk * 4];                       // conflict-free LDS.32
            float a1 = arow1[kk * 4];
            const float4 w = *(const float4*)(wp + kk * 64); // broadcast LDS.128
            acc[0] = fmaf(a0, w.x, acc[0]);
            acc[1] = fmaf(a0, w.y, acc[1]);
            acc[2] = fmaf(a0, w.z, acc[2]);
            acc[3] = fmaf(a0, w.w, acc[3]);
            acc[4] = fmaf(a1, w.x, acc[4]);
            acc[5] = fmaf(a1, w.y, acc[5]);
            acc[6] = fmaf(a1, w.z, acc[6]);
            acc[7] = fmaf(a1, w.w, acc[7]);
        }
        // stage next chunk into the other buffer
        if (ch + 1 < NCH) {
            const int nb = (ch + 1) & 1;
            float* sd = s_sm + nb * (64 * SPAD) + lrow * SPAD + lq;
            sd[0]=ra0.x; sd[1]=ra0.y; sd[2]=ra0.z; sd[3]=ra0.w;
            sd[4]=ra1.x; sd[5]=ra1.y; sd[6]=ra1.z; sd[7]=ra1.w;
            float* wd = w_sm + nb * (KC * 16) + wk * 16 + wn;
            wd[0]=rw.x; wd[1]=rw.y;
        }
        __syncthreads();
    }
}

// ---------------- persistent RHN kernel ---------------------------------
__global__ void __launch_bounds__(NTH, 1) rhn_kernel(
    const float* __restrict__ x,     // [512, 64, 1024]
    const float* __restrict__ st0,   // [2, 64, 1024]
    const float* __restrict__ w_in,  // [2, 1024, 2048]
    const float* __restrict__ w_h,   // [2, 4, 1024, 2048]
    const float* __restrict__ b_h,   // [2, 4, 2048]
    float* __restrict__ out)         // [512,64,1024] ++ [2,64,1024]
{
    __shared__ float pool[POOLSZ];

    const int c   = blockIdx.x;
    const int tid = threadIdx.x;
    const int rg  = tid & 31;
    const int cg  = (tid >> 5) & 3;
    const int ks  = tid >> 7;

    // global weight column for this thread's 4 output cols and for staging
    const int wn   = (tid & 7) * 2;
    const int wcol = (wn < 8) ? (c * CPC + wn) : (HID + c * CPC + (wn - 8));

    // gating identity: thread handles (b, j), j in [0,8)
    const int gb = tid >> 3;
    const int gj = tid & 7;
    const int gcol = c * CPC + gj;

    // init state into parity 0
    for (int i = tid; i < NLAYER * BATCH * CPC; i += NTH) {
        int l = i >> 9;
        int b = (i >> 3) & 63;
        int j = i & 7;
        int col = c * CPC + j;
        g_S[l][0][b * HID + col] = st0[(size_t)l * BATCH * HID + b * HID + col];
    }
    grid_barrier();

#pragma unroll 1
    for (int t = 0; t < SEQ; t++) {
        const float* xt = x + (size_t)t * BATCH * HID;
#pragma unroll 1
        for (int l = 0; l < NLAYER; l++) {
            const float* inp = (l == 0) ? xt : g_S[0][0];
#pragma unroll 1
            for (int d = 0; d < NDEPTH; d++) {
                const float* scur = g_S[l][d & 1];
                float*       snxt = g_S[l][(d + 1) & 1];
                const float* W = w_h + (size_t)(l * NDEPTH + d) * HID * TWOH;

                float acc[8] = {0.f,0.f,0.f,0.f,0.f,0.f,0.f,0.f};
                gemm_acc(scur, W, pool, wcol, tid, acc);
                if (d == 0) {
                    const float* Wi = w_in + (size_t)l * HID * TWOH;
                    gemm_acc(inp, Wi, pool, wcol, tid, acc);
                }

                // split-K reduction through smem (aliases s-tile region;
                // gemm_acc ended with __syncthreads so compute is done)
                float* red = pool + RED_OFF;
                {
                    float* p0 = red + ks * 1024 + rg * 16 + cg * 4;
                    p0[0] = acc[0]; p0[1] = acc[1]; p0[2] = acc[2]; p0[3] = acc[3];
                    float* p1 = red + ks * 1024 + (rg + 32) * 16 + cg * 4;
                    p1[0] = acc[4]; p1[1] = acc[5]; p1[2] = acc[6]; p1[3] = acc[7];
                }
                __syncthreads();

                // gating: thread (gb, gj) sums 4 partials for h and g, adds bias
                {
                    const float* bb = b_h + (size_t)(l * NDEPTH + d) * TWOH;
                    float hh = bb[gcol];
                    float hg = bb[HID + gcol];
                    int base = gb * 16 + gj;
#pragma unroll
                    for (int s = 0; s < 4; s++) {
                        hh += red[s * 1024 + base];
                        hg += red[s * 1024 + base + 8];
                    }
                    float hv = tanhf(hh);
                    float gv = 1.0f / (1.0f + expf(-hg));
                    float sold = __ldcg(scur + gb * HID + gcol);
                    float sn = fmaf(gv, hv - sold, sold);   // h*g + s*(1-g)
                    snxt[gb * HID + gcol] = sn;
                    if (l == NLAYER - 1 && d == NDEPTH - 1)
                        out[(size_t)t * BATCH * HID + gb * HID + gcol] = sn;
                }
                __syncthreads();          // red reads done before next pass reuses pool
                grid_barrier();
            }
        }
    }

    // final_s (both layers end each timestep at parity 0)
    const size_t fin = (size_t)SEQ * BATCH * HID;
    for (int i = tid; i < NLAYER * BATCH * CPC; i += NTH) {
        int l = i >> 9;
        int b = (i >> 3) & 63;
        int j = i & 7;
        int col = c * CPC + j;
        out[fin + (size_t)l * BATCH * HID + b * HID + col] = g_S[l][0][b * HID + col];
    }
}

// ---------------- launch -------------------------------------------------
extern "C" void kernel_launch(void* const* d_in, const int* in_sizes, int n_in,
                              void* d_out, int out_size) {
    const float* x   = (const float*)d_in[0];   // x      [512,64,1024]
    const float* st  = (const float*)d_in[1];   // state  [2,64,1024]
    const float* wi  = (const float*)d_in[2];   // w_in   [2,1024,2048]
    const float* wh  = (const float*)d_in[3];   // w_h    [2,4,1024,2048]
    const float* bh  = (const float*)d_in[4];   // b_h    [2,4,2048]
    (void)in_sizes; (void)n_in; (void)out_size;
    rhn_kernel<<<GRID, NTH>>>(x, st, wi, wh, bh, (float*)d_out);
}